// round 4
// baseline (speedup 1.0000x reference)
#include <cuda_runtime.h>
#include <cuda_bf16.h>

#define T_LEN 2048
#define E_N   19
#define B_N   64

typedef unsigned int u32;

#define C_SIG  (-1.4426950408889634f)
#define C_TANH (-2.8853900817779268f)

// final hidden states: [b][e][dir*32+l]
__device__ float g_hfinal[B_N * E_N * 64];

// 1/(1+2^a): gate pre-activations arrive pre-scaled by -log2(e) (or -2log2e)
__device__ __forceinline__ float sig_pre(float a) {
    float e, r;
    asm("ex2.approx.f32 %0, %1;" : "=f"(e) : "f"(a));
    asm("rcp.approx.f32 %0, %1;" : "=f"(r) : "f"(1.0f + e));
    return r;
}

__device__ __forceinline__ u32 pack_bf2(float lo, float hi) {
    __nv_bfloat162 p;
    p.x = __float2bfloat16(lo);   // low 16 bits = lower k index
    p.y = __float2bfloat16(hi);
    return *(u32*)&p;
}

// D += A(16x16 bf16, row) * B(16x8 bf16, col), fp32 accum
__device__ __forceinline__ void mma16816(float d[4], const u32 a[4], u32 b0, u32 b1) {
    asm volatile(
        "mma.sync.aligned.m16n8k16.row.col.f32.bf16.bf16.f32 "
        "{%0,%1,%2,%3}, {%4,%5,%6,%7}, {%8,%9}, {%0,%1,%2,%3};"
        : "+f"(d[0]), "+f"(d[1]), "+f"(d[2]), "+f"(d[3])
        : "r"(a[0]), "r"(a[1]), "r"(a[2]), "r"(a[3]), "r"(b0), "r"(b1));
}

// One warp: one (e,dir), NI batch items. Tensor-core matvec:
// gates[128 x 8cols(NI used)] = [Whi|Wlo] @ [hhi;hlo] (3-term bf16 split).
// W frags register-resident. Two smem transposes per step (gates out, h in),
// warp-local sync only.
template <int NI>
__device__ __forceinline__ void run_lstm(
    const float* __restrict__ x, const float* __restrict__ w_ih,
    const float* __restrict__ w_hh, const float* __restrict__ b_ih,
    const float* __restrict__ b_hh,
    int ed, int b0, int lane,
    float* gsm,              // [128][6] floats (row stride 6)
    __nv_bfloat16* bsm)      // [2 split][8 col][40] bf16
{
    const int e   = ed >> 1;
    const int d   = ed & 1;
    const int grp = lane >> 2;   // 0..7
    const int tig = lane & 3;    // 0..3

    // ---- build A fragments (W_hh, activation scales folded, bf16 hi/lo) ----
    u32 Ahi[8][2][4], Alo[8][2][4];
    const float* Wp = w_hh + ed * 128 * 32;
#pragma unroll
    for (int m = 0; m < 8; m++) {
        const float sc = ((m >> 1) == 2) ? C_TANH : C_SIG;
#pragma unroll
        for (int kk = 0; kk < 2; kk++) {
            const int r0 = 16 * m + grp;
            const int k0 = 16 * kk + 2 * tig;
            float w[8];
            w[0] = Wp[r0 * 32 + k0] * sc;            // (r0,   k0)
            w[1] = Wp[r0 * 32 + k0 + 1] * sc;        // (r0,   k0+1)
            w[2] = Wp[(r0 + 8) * 32 + k0] * sc;      // (r0+8, k0)
            w[3] = Wp[(r0 + 8) * 32 + k0 + 1] * sc;
            w[4] = Wp[r0 * 32 + k0 + 8] * sc;        // (r0,   k0+8)
            w[5] = Wp[r0 * 32 + k0 + 9] * sc;
            w[6] = Wp[(r0 + 8) * 32 + k0 + 8] * sc;
            w[7] = Wp[(r0 + 8) * 32 + k0 + 9] * sc;
            float hi[8], lo[8];
#pragma unroll
            for (int i = 0; i < 8; i++) {
                __nv_bfloat16 b = __float2bfloat16(w[i]);
                hi[i] = __bfloat162float(b);
                lo[i] = w[i] - hi[i];
            }
            Ahi[m][kk][0] = pack_bf2(hi[0], hi[1]);
            Ahi[m][kk][1] = pack_bf2(hi[2], hi[3]);
            Ahi[m][kk][2] = pack_bf2(hi[4], hi[5]);
            Ahi[m][kk][3] = pack_bf2(hi[6], hi[7]);
            Alo[m][kk][0] = pack_bf2(lo[0], lo[1]);
            Alo[m][kk][1] = pack_bf2(lo[2], lo[3]);
            Alo[m][kk][2] = pack_bf2(lo[4], lo[5]);
            Alo[m][kk][3] = pack_bf2(lo[6], lo[7]);
        }
    }

    // per-thread (lane = hidden unit) input weights / biases, scales folded
    float wihC[4], biasC[4];
#pragma unroll
    for (int g = 0; g < 4; g++) {
        const float Cg = (g == 2) ? C_TANH : C_SIG;
        const int row = ed * 128 + g * 32 + lane;
        wihC[g]  = Cg * w_ih[row];
        biasC[g] = Cg * (b_ih[row] + b_hh[row]);
    }

    // ---- zero h smem (h0 = 0; unused cols stay 0 forever) ----
    u32* bz = (u32*)bsm;   // 2*8*40 bf16 = 320 u32
#pragma unroll
    for (int i = 0; i < 10; i++) bz[lane + 32 * i] = 0u;

    // ---- x pointers / prefetch ----
    const int tstart = d ? (T_LEN - 1) : 0;
    const int stride = d ? -E_N : E_N;
    const float* xp[NI];
    float xc[NI], c[NI], hv[NI];
#pragma unroll
    for (int n = 0; n < NI; n++) {
        c[n] = 0.f; hv[n] = 0.f;
        xp[n] = x + ((long long)(b0 + n) * T_LEN + tstart) * E_N + e;
        xc[n] = __ldg(xp[n]);
    }
    __syncwarp();

    // B-frag smem addresses for this thread (col = grp, k rows = 2*tig base)
    const __nv_bfloat16* b_hi = &bsm[0 * 8 * 40 + grp * 40 + 2 * tig];
    const __nv_bfloat16* b_lo = &bsm[1 * 8 * 40 + grp * 40 + 2 * tig];

#pragma unroll 1
    for (int t = 0; t < T_LEN; t++) {
        // ---- B fragments (h from previous step; zeros at t=0) ----
        u32 Bh0a = *(const u32*)(b_hi);        // ktile0: rows 2tig, 2tig+1
        u32 Bh0b = *(const u32*)(b_hi + 8);    //         rows +8
        u32 Bh1a = *(const u32*)(b_hi + 16);   // ktile1
        u32 Bh1b = *(const u32*)(b_hi + 24);
        u32 Bl0a = *(const u32*)(b_lo);
        u32 Bl0b = *(const u32*)(b_lo + 8);
        u32 Bl1a = *(const u32*)(b_lo + 16);
        u32 Bl1b = *(const u32*)(b_lo + 24);

        // prefetch next x
        float xn[NI];
        if (t < T_LEN - 1) {
#pragma unroll
            for (int n = 0; n < NI; n++) xp[n] += stride;
        }
#pragma unroll
        for (int n = 0; n < NI; n++) xn[n] = __ldg(xp[n]);

        // ---- 48 HMMA: gates = Whi*hhi + Wlo*hhi + Whi*hlo ----
        float D[8][4];
#pragma unroll
        for (int m = 0; m < 8; m++) {
            D[m][0] = 0.f; D[m][1] = 0.f; D[m][2] = 0.f; D[m][3] = 0.f;
            mma16816(D[m], Ahi[m][0], Bh0a, Bh0b);
            mma16816(D[m], Ahi[m][1], Bh1a, Bh1b);
            mma16816(D[m], Alo[m][0], Bh0a, Bh0b);
            mma16816(D[m], Alo[m][1], Bh1a, Bh1b);
            mma16816(D[m], Ahi[m][0], Bl0a, Bl0b);
            mma16816(D[m], Ahi[m][1], Bl1a, Bl1b);
        }

        // ---- transpose gates to lane=hidden layout via smem ----
        if (tig == 0) {
#pragma unroll
            for (int m = 0; m < 8; m++) {
                const int r = 16 * m + grp;
                *(float2*)&gsm[r * 6]       = make_float2(D[m][0], D[m][1]);
                *(float2*)&gsm[(r + 8) * 6] = make_float2(D[m][2], D[m][3]);
            }
        }
        if (NI == 3 && tig == 1) {
#pragma unroll
            for (int m = 0; m < 8; m++) {
                const int r = 16 * m + grp;
                gsm[r * 6 + 2]       = D[m][0];   // col 2
                gsm[(r + 8) * 6 + 2] = D[m][2];
            }
        }
        __syncwarp();

        float2 gv[4]; float g2[4];
#pragma unroll
        for (int g = 0; g < 4; g++) {
            gv[g] = *(const float2*)&gsm[(g * 32 + lane) * 6];
            if (NI == 3) g2[g] = gsm[(g * 32 + lane) * 6 + 2];
        }

        // ---- activations + c/h update, write h hi/lo back for next B ----
#pragma unroll
        for (int n = 0; n < NI; n++) {
            float ai, af, ag, ao;
            if (n == 0)      { ai = gv[0].x; af = gv[1].x; ag = gv[2].x; ao = gv[3].x; }
            else if (n == 1) { ai = gv[0].y; af = gv[1].y; ag = gv[2].y; ao = gv[3].y; }
            else             { ai = g2[0];   af = g2[1];   ag = g2[2];   ao = g2[3];   }
            ai += fmaf(xc[n], wihC[0], biasC[0]);
            af += fmaf(xc[n], wihC[1], biasC[1]);
            ag += fmaf(xc[n], wihC[2], biasC[2]);
            ao += fmaf(xc[n], wihC[3], biasC[3]);
            const float si = sig_pre(ai);
            const float sf = sig_pre(af);
            const float tg = fmaf(2.f, sig_pre(ag), -1.f);
            const float so = sig_pre(ao);
            c[n] = fmaf(sf, c[n], si * tg);
            const float tc = fmaf(2.f, sig_pre(c[n] * C_TANH), -1.f);
            const float h = so * tc;
            hv[n] = h;
            const __nv_bfloat16 bh = __float2bfloat16(h);
            const __nv_bfloat16 bl = __float2bfloat16(h - __bfloat162float(bh));
            bsm[0 * 8 * 40 + n * 40 + lane] = bh;
            bsm[1 * 8 * 40 + n * 40 + lane] = bl;
        }
        __syncwarp();

#pragma unroll
        for (int n = 0; n < NI; n++) xc[n] = xn[n];
    }

#pragma unroll
    for (int n = 0; n < NI; n++)
        g_hfinal[((b0 + n) * E_N + e) * 64 + d * 32 + lane] = hv[n];
}

// 296 CTAs x 4 warps = 1184 warps, exactly 2 warps/SMSP.
// eds 0..31 -> 31 warps (k<29: NI=2, k=29/30: NI=3); eds 32..37 -> 32 warps NI=2.
__global__ void __launch_bounds__(128, 2)
lstm_kernel(const float* __restrict__ x,
            const float* __restrict__ w_ih,
            const float* __restrict__ w_hh,
            const float* __restrict__ b_ih,
            const float* __restrict__ b_hh)
{
    __shared__ float gsm_all[4][128 * 6];
    __shared__ __nv_bfloat16 bsm_all[4][2 * 8 * 40];

    const int wid  = threadIdx.x >> 5;
    const int lane = threadIdx.x & 31;
    const int W    = blockIdx.x * 4 + wid;

    int ed, k;
    if (W < 992) { ed = W / 31; k = W - ed * 31; }
    else         { int r = W - 992; ed = 32 + (r >> 5); k = r & 31; }

    if (W < 992 && k >= 29) {
        run_lstm<3>(x, w_ih, w_hh, b_ih, b_hh, ed, 58 + 3 * (k - 29), lane,
                    gsm_all[wid], bsm_all[wid]);
    } else {
        run_lstm<2>(x, w_ih, w_hh, b_ih, b_hh, ed, 2 * k, lane,
                    gsm_all[wid], bsm_all[wid]);
    }
}

// Per-batch epilogue: per-electrode LayerNorm over 64 features, electrode mean, FC.
__global__ void __launch_bounds__(64)
head_kernel(const float* __restrict__ ln_gamma,
            const float* __restrict__ ln_beta,
            const float* __restrict__ fc_w,
            const float* __restrict__ fc_b,
            float* __restrict__ out)
{
    const int b = blockIdx.x;
    const int f = threadIdx.x;
    __shared__ float red[4];
    const float* hbp = g_hfinal + b * (E_N * 64);

    float pooled = 0.f;
    for (int e = 0; e < E_N; e++) {
        float v = hbp[e * 64 + f];
        float s = v, s2 = v * v;
#pragma unroll
        for (int off = 16; off; off >>= 1) {
            s  += __shfl_xor_sync(0xffffffffu, s,  off);
            s2 += __shfl_xor_sync(0xffffffffu, s2, off);
        }
        if ((f & 31) == 0) { red[(f >> 5) * 2] = s; red[(f >> 5) * 2 + 1] = s2; }
        __syncthreads();
        float S = red[0] + red[2], S2 = red[1] + red[3];
        __syncthreads();
        float mu  = S * (1.0f / 64.0f);
        float var = fmaf(-mu, mu, S2 * (1.0f / 64.0f));
        float nv  = (v - mu) * rsqrtf(var + 1e-5f);
        pooled += fmaf(nv, ln_gamma[e * 64 + f], ln_beta[e * 64 + f]);
    }
    pooled *= (1.0f / (float)E_N);

    float a = pooled * fc_w[f];
#pragma unroll
    for (int off = 16; off; off >>= 1) a += __shfl_xor_sync(0xffffffffu, a, off);
    if ((f & 31) == 0) red[f >> 5] = a;
    __syncthreads();
    if (f == 0) out[b] = red[0] + red[1] + fc_b[0];
}

extern "C" void kernel_launch(void* const* d_in, const int* in_sizes, int n_in,
                              void* d_out, int out_size) {
    const float* x        = (const float*)d_in[0];
    const float* w_ih     = (const float*)d_in[1];
    const float* w_hh     = (const float*)d_in[2];
    const float* b_ih     = (const float*)d_in[3];
    const float* b_hh     = (const float*)d_in[4];
    const float* ln_gamma = (const float*)d_in[5];
    const float* ln_beta  = (const float*)d_in[6];
    const float* fc_w     = (const float*)d_in[7];
    const float* fc_b     = (const float*)d_in[8];
    float* out = (float*)d_out;

    lstm_kernel<<<296, 128>>>(x, w_ih, w_hh, b_ih, b_hh);
    head_kernel<<<B_N, 64>>>(ln_gamma, ln_beta, fc_w, fc_b, out);
}